// round 12
// baseline (speedup 1.0000x reference)
#include <cuda_runtime.h>
#include <cstddef>

// Problem constants (fixed by the dataset)
constexpr int Bc  = 4;
constexpr int Tc  = 2048;
constexpr int Dc  = 512;
constexpr int Hc  = 8;
constexpr int DKc = 64;   // Dc / Hc

// -------------------- scratch (device globals; no allocation allowed) ------
__device__ float g_Q[(size_t)Bc * Tc * Dc];   // Q projection (b,t,h*dk)
__device__ float g_K[(size_t)Bc * Tc * Dc];   // K projection, then Kp = K + P in-place
__device__ float g_V[(size_t)Bc * Tc * Dc];   // V projection
__device__ float g_P[(size_t)Tc * Dc];        // pos projection
__device__ float g_C[(size_t)Bc * Hc * Tc];   // per-(b,h,s) score bias  u.k + v.p
__device__ float g_X[(size_t)Bc * Tc * Dc];   // attention output before Wo

// ---------------------------------------------------------------------------
// GEMM: out[M,N] = A[M,K] @ W[N,K]^T (+ bias[N]).  Tiles 64x64x16, 256 thr,
// 4x4 microtile. Smem stored transposed [k][idx] with stride 68 (16B aligned,
// conflict-free float4 reads).
// ---------------------------------------------------------------------------
__global__ __launch_bounds__(256) void gemm_bias_kernel(
    const float* __restrict__ A, const float* __restrict__ W,
    const float* __restrict__ bias, float* __restrict__ out,
    int M, int N, int K)
{
    __shared__ float As[16 * 68];
    __shared__ float Ws[16 * 68];

    const int tid = threadIdx.x;
    const int tx = tid & 15, ty = tid >> 4;
    const int m0 = blockIdx.y << 6, n0 = blockIdx.x << 6;
    const int lr = tid >> 2;            // 0..63 (row within tile)
    const int lc = (tid & 3) << 2;      // 0,4,8,12 (k offset within tile)

    const float* Ap = A + (size_t)(m0 + lr) * K + lc;
    const float* Wp = W + (size_t)(n0 + lr) * K + lc;

    float acc[4][4];
#pragma unroll
    for (int i = 0; i < 4; i++)
#pragma unroll
        for (int j = 0; j < 4; j++) acc[i][j] = 0.f;

    for (int k0 = 0; k0 < K; k0 += 16) {
        float4 av = *(const float4*)(Ap + k0);
        float4 wv = *(const float4*)(Wp + k0);
        __syncthreads();            // previous compute done before overwrite
        As[(lc + 0) * 68 + lr] = av.x;
        As[(lc + 1) * 68 + lr] = av.y;
        As[(lc + 2) * 68 + lr] = av.z;
        As[(lc + 3) * 68 + lr] = av.w;
        Ws[(lc + 0) * 68 + lr] = wv.x;
        Ws[(lc + 1) * 68 + lr] = wv.y;
        Ws[(lc + 2) * 68 + lr] = wv.z;
        Ws[(lc + 3) * 68 + lr] = wv.w;
        __syncthreads();
#pragma unroll
        for (int k = 0; k < 16; k++) {
            float4 a  = *(const float4*)&As[k * 68 + (ty << 2)];
            float4 bb = *(const float4*)&Ws[k * 68 + (tx << 2)];
            float ar[4] = {a.x, a.y, a.z, a.w};
            float br[4] = {bb.x, bb.y, bb.z, bb.w};
#pragma unroll
            for (int i = 0; i < 4; i++)
#pragma unroll
                for (int j = 0; j < 4; j++)
                    acc[i][j] = fmaf(ar[i], br[j], acc[i][j]);
        }
    }

#pragma unroll
    for (int i = 0; i < 4; i++) {
        const int m = m0 + (ty << 2) + i;
        float* op = out + (size_t)m * N + n0 + (tx << 2);
#pragma unroll
        for (int j = 0; j < 4; j++) {
            float bv = bias ? bias[n0 + (tx << 2) + j] : 0.f;
            op[j] = acc[i][j] + bv;
        }
    }
}

// ---------------------------------------------------------------------------
// Fuse: Kp = K + P (in place), C[b,h,s] = sum_d u[h,d]*K + v[h,d]*P
// One block per (b,s), 512 threads (one per d).
// ---------------------------------------------------------------------------
__global__ __launch_bounds__(512) void kp_c_kernel(
    float* __restrict__ K, const float* __restrict__ P,
    const float* __restrict__ u, const float* __restrict__ v,
    float* __restrict__ C)
{
    __shared__ float prod[512];
    const int bs = blockIdx.x;
    const int s  = bs & (Tc - 1);
    const int d  = threadIdx.x;

    const size_t kidx = (size_t)bs * Dc + d;
    float kv = K[kidx];
    float pv = P[(size_t)s * Dc + d];
    K[kidx] = kv + pv;
    prod[d] = u[d] * kv + v[d] * pv;   // d = h*64 + dk, matches (H,DK) flatten
    __syncthreads();
#pragma unroll
    for (int off = 32; off > 0; off >>= 1) {
        if ((d & 63) < off) prod[d] += prod[d + off];
        __syncthreads();
    }
    if ((d & 63) == 0) {
        const int b = bs >> 11;        // bs / Tc
        C[((size_t)b * Hc + (d >> 6)) * Tc + s] = prod[d];
    }
}

// ---------------------------------------------------------------------------
// Flash attention (fp32). Block = (b, h, 64-query tile), 256 threads.
// scores[t,s] = (q[t] . Kp[s] + C[s]) / 8 ; online softmax ; O += P @ V.
// ---------------------------------------------------------------------------
constexpr int ATTN_SMEM_FLOATS = 3 * 64 * 68 + 64 * 64 + 64 + 64;
constexpr int ATTN_SMEM_BYTES  = ATTN_SMEM_FLOATS * 4;   // 69120

__global__ __launch_bounds__(256) void attn_kernel(
    const float* __restrict__ Q, const float* __restrict__ Kp,
    const float* __restrict__ V, const float* __restrict__ C,
    const int* __restrict__ mask, float* __restrict__ X)
{
    extern __shared__ float sm[];
    float* Qs = sm;                  // [d][tq]  stride 68
    float* Ks = sm + 64 * 68;        // [d][ts]  stride 68
    float* Ps = sm + 2 * 64 * 68;    // [ts][tq] stride 68
    float* Vs = sm + 3 * 64 * 68;    // [ts][dv] stride 64
    float* Cs = Vs + 64 * 64;        // [64]
    float* Ms = Cs + 64;             // [64]

    const int tid = threadIdx.x;
    const int tx = tid & 15, ty = tid >> 4;
    const int b = blockIdx.z, h = blockIdx.y;
    const int t0 = blockIdx.x << 6;
    const int lr = tid >> 2, lcg = tid & 3;

    // Load Q tile transposed into smem
    {
        const float* qb = Q + ((size_t)(b * Tc + t0 + lr)) * Dc + h * DKc;
#pragma unroll
        for (int c = 0; c < 4; c++) {
            const int dd = lcg * 16 + c * 4;
            float4 qv = *(const float4*)(qb + dd);
            Qs[(dd + 0) * 68 + lr] = qv.x;
            Qs[(dd + 1) * 68 + lr] = qv.y;
            Qs[(dd + 2) * 68 + lr] = qv.z;
            Qs[(dd + 3) * 68 + lr] = qv.w;
        }
    }

    float m_i[4], l_i[4], oacc[4][4];
#pragma unroll
    for (int i = 0; i < 4; i++) {
        m_i[i] = -1e30f; l_i[i] = 0.f;
#pragma unroll
        for (int j = 0; j < 4; j++) oacc[i][j] = 0.f;
    }

    for (int s0 = 0; s0 < Tc; s0 += 64) {
        // Load K (transposed), V (natural), C, mask for this s-tile
        {
            const float* kb = Kp + ((size_t)(b * Tc + s0 + lr)) * Dc + h * DKc;
            const float* vb = V  + ((size_t)(b * Tc + s0 + lr)) * Dc + h * DKc;
#pragma unroll
            for (int c = 0; c < 4; c++) {
                const int dd = lcg * 16 + c * 4;
                float4 kv = *(const float4*)(kb + dd);
                Ks[(dd + 0) * 68 + lr] = kv.x;
                Ks[(dd + 1) * 68 + lr] = kv.y;
                Ks[(dd + 2) * 68 + lr] = kv.z;
                Ks[(dd + 3) * 68 + lr] = kv.w;
                float4 vv = *(const float4*)(vb + dd);
                *(float4*)&Vs[lr * 64 + dd] = vv;
            }
            if (tid < 64) {
                Cs[tid] = C[((size_t)b * Hc + h) * Tc + s0 + tid];
                Ms[tid] = (float)mask[b * Tc + s0 + tid];
            }
        }
        __syncthreads();   // tiles ready (also covers Q stores on first iter)

        // S = Q . Kp^T  (per-thread 4x4 microtile)
        float sacc[4][4];
#pragma unroll
        for (int i = 0; i < 4; i++)
#pragma unroll
            for (int j = 0; j < 4; j++) sacc[i][j] = 0.f;

#pragma unroll 8
        for (int d = 0; d < 64; d++) {
            float4 a  = *(const float4*)&Qs[d * 68 + (ty << 2)];
            float4 bb = *(const float4*)&Ks[d * 68 + (tx << 2)];
            float ar[4] = {a.x, a.y, a.z, a.w};
            float br[4] = {bb.x, bb.y, bb.z, bb.w};
#pragma unroll
            for (int i = 0; i < 4; i++)
#pragma unroll
                for (int j = 0; j < 4; j++)
                    sacc[i][j] = fmaf(ar[i], br[j], sacc[i][j]);
        }

        // Online softmax (rows reduced across the 16 tx lanes of each half-warp)
        float cj[4], mk[4];
#pragma unroll
        for (int j = 0; j < 4; j++) {
            cj[j] = Cs[(tx << 2) + j];
            mk[j] = Ms[(tx << 2) + j];
        }
#pragma unroll
        for (int i = 0; i < 4; i++) {
            float sv[4];
#pragma unroll
            for (int j = 0; j < 4; j++)
                sv[j] = (mk[j] != 0.f) ? (sacc[i][j] + cj[j]) * 0.125f : -1e30f;
            float tmax = fmaxf(fmaxf(sv[0], sv[1]), fmaxf(sv[2], sv[3]));
#pragma unroll
            for (int off = 8; off > 0; off >>= 1)
                tmax = fmaxf(tmax, __shfl_xor_sync(0xffffffffu, tmax, off));
            float mnew  = fmaxf(m_i[i], tmax);
            float alpha = __expf(m_i[i] - mnew);
            m_i[i] = mnew;
            float rs = 0.f;
#pragma unroll
            for (int j = 0; j < 4; j++) {
                float p = (mk[j] != 0.f) ? __expf(sv[j] - mnew) : 0.f;
                rs += p;
                Ps[((tx << 2) + j) * 68 + (ty << 2) + i] = p;
            }
#pragma unroll
            for (int off = 8; off > 0; off >>= 1)
                rs += __shfl_xor_sync(0xffffffffu, rs, off);
            l_i[i] = l_i[i] * alpha + rs;
#pragma unroll
            for (int j = 0; j < 4; j++) oacc[i][j] *= alpha;
        }
        __syncthreads();   // Ps visible to all

        // O += P @ V
#pragma unroll 8
        for (int ts = 0; ts < 64; ts++) {
            float4 a  = *(const float4*)&Ps[ts * 68 + (ty << 2)];
            float4 bb = *(const float4*)&Vs[ts * 64 + (tx << 2)];
            float ar[4] = {a.x, a.y, a.z, a.w};
            float br[4] = {bb.x, bb.y, bb.z, bb.w};
#pragma unroll
            for (int i = 0; i < 4; i++)
#pragma unroll
                for (int j = 0; j < 4; j++)
                    oacc[i][j] = fmaf(ar[i], br[j], oacc[i][j]);
        }
        __syncthreads();   // done with tiles before next iteration overwrites
    }

    // Normalize and write X
#pragma unroll
    for (int i = 0; i < 4; i++) {
        float inv = (l_i[i] > 0.f) ? (1.f / l_i[i]) : 0.f;
        float* xp = X + ((size_t)(b * Tc + t0 + (ty << 2) + i)) * Dc
                      + h * DKc + (tx << 2);
#pragma unroll
        for (int j = 0; j < 4; j++) xp[j] = oacc[i][j] * inv;
    }
}

// ---------------------------------------------------------------------------
extern "C" void kernel_launch(void* const* d_in, const int* in_sizes, int n_in,
                              void* d_out, int out_size)
{
    (void)in_sizes; (void)n_in; (void)out_size;
    const float* query = (const float*)d_in[0];
    const float* key   = (const float*)d_in[1];
    const float* value = (const float*)d_in[2];
    const int*   mask  = (const int*)  d_in[3];
    const float* pos   = (const float*)d_in[4];
    const float* Wq    = (const float*)d_in[5];
    const float* bq    = (const float*)d_in[6];
    const float* Wk    = (const float*)d_in[7];
    const float* bk    = (const float*)d_in[8];
    const float* Wv    = (const float*)d_in[9];
    const float* bv    = (const float*)d_in[10];
    const float* Wo    = (const float*)d_in[11];
    const float* bo    = (const float*)d_in[12];
    const float* Wp    = (const float*)d_in[13];
    const float* u     = (const float*)d_in[14];
    const float* v     = (const float*)d_in[15];
    float* out = (float*)d_out;

    float *Qb, *Kb, *Vb, *Pb, *Cb, *Xb;
    cudaGetSymbolAddress((void**)&Qb, g_Q);
    cudaGetSymbolAddress((void**)&Kb, g_K);
    cudaGetSymbolAddress((void**)&Vb, g_V);
    cudaGetSymbolAddress((void**)&Pb, g_P);
    cudaGetSymbolAddress((void**)&Cb, g_C);
    cudaGetSymbolAddress((void**)&Xb, g_X);

    cudaFuncSetAttribute(attn_kernel,
                         cudaFuncAttributeMaxDynamicSharedMemorySize,
                         ATTN_SMEM_BYTES);

    // P = pos_emb @ Wp^T (no bias)
    gemm_bias_kernel<<<dim3(Dc / 64, Tc / 64), 256>>>(pos, Wp, nullptr, Pb, Tc, Dc, Dc);
    // Q/K/V projections
    gemm_bias_kernel<<<dim3(Dc / 64, (Bc * Tc) / 64), 256>>>(query, Wq, bq, Qb, Bc * Tc, Dc, Dc);
    gemm_bias_kernel<<<dim3(Dc / 64, (Bc * Tc) / 64), 256>>>(key,   Wk, bk, Kb, Bc * Tc, Dc, Dc);
    gemm_bias_kernel<<<dim3(Dc / 64, (Bc * Tc) / 64), 256>>>(value, Wv, bv, Vb, Bc * Tc, Dc, Dc);
    // Kp = K + P (in place) and per-(b,h,s) bias C = u.k + v.p
    kp_c_kernel<<<Bc * Tc, Dc>>>(Kb, Pb, u, v, Cb);
    // Flash attention
    attn_kernel<<<dim3(Tc / 64, Hc, Bc), 256, ATTN_SMEM_BYTES>>>(Qb, Kb, Vb, Cb, mask, Xb);
    // Output projection
    gemm_bias_kernel<<<dim3(Dc / 64, (Bc * Tc) / 64), 256>>>(Xb, Wo, bo, out, Bc * Tc, Dc, Dc);
}